// round 1
// baseline (speedup 1.0000x reference)
#include <cuda_runtime.h>
#include <math.h>

// Problem constants (fixed by the reference).
constexpr int NTOK = 8192;   // N
constexpr int D_   = 512;
constexpr int H1_  = 1024;
constexpr int H2_  = 512;
constexpr int NC_  = 10;     // classes
constexpr int NSPLIT = 32;   // row splits for column stats

// ---------------- device scratch (static globals: the sanctioned scratch path) ---------
__device__ float g_xn[(size_t)NTOK * D_];          // 16 MB  normalized input
__device__ float g_h1[(size_t)NTOK * H1_];         // 32 MB  layer-1 activations (in-place BN)
__device__ float g_f [(size_t)NTOK * H2_];         // 16 MB  final features (in-place BN)
__device__ float g_S [(size_t)NTOK * NTOK];        // 268 MB similarity matrix
__device__ float g_sqn[NTOK];                      // row squared norms of f
__device__ float g_psum[NSPLIT * H1_];             // column-stat partials (max width H1)
__device__ float g_psq [NSPLIT * H1_];
__device__ float g_scale[H1_];                     // BN affine: y = x*scale + shift
__device__ float g_shift[H1_];

// ---------------- column stats: partial sums per (col, row-split) ----------------------
// STAGE 0: input x (external ptr), ncols=D_.  STAGE 1: g_h1, ncols=H1_.  STAGE 2: g_f, ncols=H2_.
template <int STAGE>
__global__ __launch_bounds__(256) void colstats_k(const float* __restrict__ ext) {
    constexpr int NC = (STAGE == 0) ? D_ : (STAGE == 1 ? H1_ : H2_);
    const float* __restrict__ X = (STAGE == 0) ? ext : (STAGE == 1 ? g_h1 : g_f);
    const int lane = threadIdx.x & 31;
    const int warp = threadIdx.x >> 5;          // 0..7
    const int col  = blockIdx.x * 32 + lane;
    constexpr int RPS = NTOK / NSPLIT;          // 256 rows per split
    const int r0 = blockIdx.y * RPS;

    float s = 0.f, q = 0.f;
    for (int r = warp; r < RPS; r += 8) {
        float v = X[(size_t)(r0 + r) * NC + col];
        s += v;
        q += v * v;
    }
    __shared__ float shs[8][32];
    __shared__ float shq[8][32];
    shs[warp][lane] = s;
    shq[warp][lane] = q;
    __syncthreads();
    if (warp == 0) {
        float ts = 0.f, tq = 0.f;
#pragma unroll
        for (int w = 0; w < 8; w++) { ts += shs[w][lane]; tq += shq[w][lane]; }
        g_psum[blockIdx.y * NC + col] = ts;
        g_psq [blockIdx.y * NC + col] = tq;
    }
}

// ---------------- finalize stats -> scale/shift (double precision combine) -------------
__global__ void colfinish_k(int ncols, const float* __restrict__ g, const float* __restrict__ b) {
    int col = blockIdx.x * 256 + threadIdx.x;
    if (col >= ncols) return;
    double s = 0.0, q = 0.0;
    for (int p = 0; p < NSPLIT; p++) {
        s += (double)g_psum[p * ncols + col];
        q += (double)g_psq [p * ncols + col];
    }
    double mu  = s / (double)NTOK;
    double var = q / (double)NTOK - mu * mu;        // biased variance (matches reference)
    double sc  = (double)g[col] / sqrt(var + 1e-5);
    g_scale[col] = (float)sc;
    g_shift[col] = (float)((double)b[col] - mu * sc);
}

// ---------------- apply BN affine elementwise (float4) ---------------------------------
// STAGE 0: x(ext) -> g_xn.  STAGE 1: g_h1 in place.  STAGE 2: g_f in place.
template <int STAGE>
__global__ __launch_bounds__(256) void bn_apply_k(const float* __restrict__ ext) {
    constexpr int NC = (STAGE == 0) ? D_ : (STAGE == 1 ? H1_ : H2_);
    const float* __restrict__ in = (STAGE == 0) ? ext : (STAGE == 1 ? g_h1 : g_f);
    float* __restrict__ outp     = (STAGE == 0) ? g_xn : (STAGE == 1 ? g_h1 : g_f);
    constexpr int TOT4 = NTOK * NC / 4;
    for (int i = blockIdx.x * blockDim.x + threadIdx.x; i < TOT4; i += gridDim.x * blockDim.x) {
        float4 v = reinterpret_cast<const float4*>(in)[i];
        int col = (i * 4) & (NC - 1);                 // NC is a power of 2
        v.x = fmaf(v.x, g_scale[col + 0], g_shift[col + 0]);
        v.y = fmaf(v.y, g_scale[col + 1], g_shift[col + 1]);
        v.z = fmaf(v.z, g_scale[col + 2], g_shift[col + 2]);
        v.w = fmaf(v.w, g_scale[col + 3], g_shift[col + 3]);
        reinterpret_cast<float4*>(outp)[i] = v;
    }
}

// ---------------- row squared norms of f ------------------------------------------------
__global__ __launch_bounds__(256) void rowsq_k() {
    int row  = blockIdx.x * 8 + (threadIdx.x >> 5);
    int lane = threadIdx.x & 31;
    float s = 0.f;
#pragma unroll
    for (int k = lane; k < H2_; k += 32) {
        float v = g_f[(size_t)row * H2_ + k];
        s = fmaf(v, v, s);
    }
#pragma unroll
    for (int o = 16; o; o >>= 1) s += __shfl_down_sync(0xffffffffu, s, o);
    if (!lane) g_sqn[row] = s;
}

// ---------------- tiled SGEMM (NT): C[i,j] = op(dot(A_i, B_j)) --------------------------
// MODE 0: A=g_xn [8192,512],  B=W1 [1024,512],  C=g_h1 = tanh(dot+b1)
// MODE 1: A=g_h1 [8192,1024], B=W2 [512,1024],  C=g_f  = tanh(dot+b2)
// MODE 2: A=B=g_f [8192,512], C=g_S = -dist (diag -inf)
template <int MODE>
__global__ __launch_bounds__(256) void gemm_k(const float* __restrict__ Bext,
                                              const float* __restrict__ bias) {
    constexpr int N = (MODE == 0) ? H1_ : (MODE == 1 ? H2_ : NTOK);
    constexpr int K = (MODE == 1) ? H1_ : D_;
    const float* __restrict__ A = (MODE == 0) ? g_xn : (MODE == 1 ? g_h1 : g_f);
    const float* __restrict__ B = (MODE == 2) ? g_f : Bext;
    float* __restrict__ C       = (MODE == 0) ? g_h1 : (MODE == 1 ? g_f : g_S);

    __shared__ float As[16][136];   // +8 pad: conflict-free transposed stores, 16B-aligned rows
    __shared__ float Bs[16][136];

    const int tid  = threadIdx.x;
    const int brow = blockIdx.y * 128;
    const int bcol = blockIdx.x * 128;
    const int tr   = (tid >> 4) << 3;      // 0..120
    const int tc   = (tid & 15) << 3;      // 0..120
    const int lr   = tid >> 2;             // 0..63
    const int lc   = (tid & 3) << 2;       // 0,4,8,12

    float acc[8][8] = {};

    for (int k0 = 0; k0 < K; k0 += 16) {
#pragma unroll
        for (int h = 0; h < 2; h++) {
            int r = lr + h * 64;
            float4 va = *reinterpret_cast<const float4*>(A + (size_t)(brow + r) * K + k0 + lc);
            As[lc + 0][r] = va.x; As[lc + 1][r] = va.y; As[lc + 2][r] = va.z; As[lc + 3][r] = va.w;
            float4 vb = *reinterpret_cast<const float4*>(B + (size_t)(bcol + r) * K + k0 + lc);
            Bs[lc + 0][r] = vb.x; Bs[lc + 1][r] = vb.y; Bs[lc + 2][r] = vb.z; Bs[lc + 3][r] = vb.w;
        }
        __syncthreads();
#pragma unroll
        for (int kk = 0; kk < 16; kk++) {
            float ar[8], br[8];
#pragma unroll
            for (int i = 0; i < 8; i++) ar[i] = As[kk][tr + i];
#pragma unroll
            for (int j = 0; j < 8; j++) br[j] = Bs[kk][tc + j];
#pragma unroll
            for (int i = 0; i < 8; i++)
#pragma unroll
                for (int j = 0; j < 8; j++)
                    acc[i][j] = fmaf(ar[i], br[j], acc[i][j]);
        }
        __syncthreads();
    }

    if constexpr (MODE == 2) {
#pragma unroll
        for (int i = 0; i < 8; i++) {
            int gi = brow + tr + i;
            float sqi = g_sqn[gi];
#pragma unroll
            for (int j = 0; j < 8; j++) {
                int gj = bcol + tc + j;
                float d2 = fmaxf(sqi + g_sqn[gj] - 2.f * acc[i][j], 0.f);
                float s  = (d2 > 1e-9f) ? -sqrtf(d2) : 0.f;   // matches reference guard
                if (gi == gj) s = -INFINITY;                  // self-neighbor mask
                C[(size_t)gi * NTOK + gj] = s;
            }
        }
    } else {
#pragma unroll
        for (int i = 0; i < 8; i++) {
            int gi = brow + tr + i;
#pragma unroll
            for (int j = 0; j < 8; j++) {
                int gj = bcol + tc + j;
                C[(size_t)gi * N + gj] = tanhf(acc[i][j] + bias[gj]);
            }
        }
    }
}

// ---------------- per-row top-64 + softmax + one-hot scatter ----------------------------
__global__ __launch_bounds__(256) void topk_k(const int* __restrict__ yn, float* __restrict__ out) {
    const int row  = blockIdx.x;
    const float* __restrict__ srow = g_S + (size_t)row * NTOK;
    const int tid  = threadIdx.x;
    const int lane = tid & 31;
    const int warp = tid >> 5;

    // Each thread owns 32 strided values of the row: global index = tid + k*256.
    float v[32];
#pragma unroll
    for (int k = 0; k < 32; k++) v[k] = srow[tid + (k << 8)];

    float lm = -INFINITY; int li = 0;
#pragma unroll
    for (int k = 0; k < 32; k++) if (v[k] > lm) { lm = v[k]; li = k; }

    __shared__ float swv[8];
    __shared__ int   swi[8];
    __shared__ int   sbroad;
    __shared__ float wval[64];
    __shared__ int   widx[64];

    for (int it = 0; it < 64; it++) {
        float bv = lm;
        int   bi = tid + (li << 8);
#pragma unroll
        for (int o = 16; o; o >>= 1) {
            float ov = __shfl_down_sync(0xffffffffu, bv, o);
            int   oi = __shfl_down_sync(0xffffffffu, bi, o);
            if (ov > bv || (ov == bv && oi < bi)) { bv = ov; bi = oi; }   // tie -> lower index
        }
        if (!lane) { swv[warp] = bv; swi[warp] = bi; }
        __syncthreads();
        if (!tid) {
            float wv = swv[0]; int wi = swi[0];
#pragma unroll
            for (int w = 1; w < 8; w++)
                if (swv[w] > wv || (swv[w] == wv && swi[w] < wi)) { wv = swv[w]; wi = swi[w]; }
            wval[it] = wv; widx[it] = wi; sbroad = wi;
        }
        __syncthreads();
        int wi = sbroad;
        if ((wi & 255) == tid) {          // owner removes winner, recomputes local max
            v[wi >> 8] = -INFINITY;
            lm = -INFINITY; li = 0;
#pragma unroll
            for (int k = 0; k < 32; k++) if (v[k] > lm) { lm = v[k]; li = k; }
        }
    }
    __syncthreads();

    __shared__ float earr[64];
    __shared__ int   larr[64];
    if (tid < 64) {
        earr[tid] = expf(wval[tid] - wval[0]);   // wval[0] is the row max (descending order)
        larr[tid] = yn[widx[tid]];
    }
    __syncthreads();

    __shared__ float bins[NC_];
    __shared__ float tot;
    if (!tid) {                                   // serial: deterministic accumulation
        float bb[NC_];
#pragma unroll
        for (int c = 0; c < NC_; c++) bb[c] = 0.f;
        float t = 0.f;
        for (int k = 0; k < 64; k++) { t += earr[k]; bb[larr[k]] += earr[k]; }
        tot = t;
#pragma unroll
        for (int c = 0; c < NC_; c++) bins[c] = bb[c];
    }
    __syncthreads();
    if (tid < NC_) {
        float p = bins[tid] / tot;
        out[(size_t)row * NC_ + tid] = fminf(fmaxf(p, 0.f), 1.f);
    }
}

// ---------------- launcher --------------------------------------------------------------
extern "C" void kernel_launch(void* const* d_in, const int* in_sizes, int n_in,
                              void* d_out, int out_size) {
    (void)in_sizes; (void)n_in; (void)out_size;
    const float* x     = (const float*)d_in[0];
    // d_in[1] is x_n == x elementwise (reference guarantees it) -> features computed once
    const int*   y_n   = (const int*)  d_in[2];
    const float* ibn_g = (const float*)d_in[3];
    const float* ibn_b = (const float*)d_in[4];
    const float* W1    = (const float*)d_in[5];
    const float* b1    = (const float*)d_in[6];
    const float* g1    = (const float*)d_in[7];
    const float* bb1   = (const float*)d_in[8];
    const float* W2    = (const float*)d_in[9];
    const float* b2    = (const float*)d_in[10];
    const float* g2    = (const float*)d_in[11];
    const float* bb2   = (const float*)d_in[12];
    float* out = (float*)d_out;

    // input BN
    colstats_k<0><<<dim3(D_ / 32, NSPLIT), 256>>>(x);
    colfinish_k<<<(D_ + 255) / 256, 256>>>(D_, ibn_g, ibn_b);
    bn_apply_k<0><<<2048, 256>>>(x);

    // layer 1: Linear -> tanh -> BN
    gemm_k<0><<<dim3(H1_ / 128, NTOK / 128), 256>>>(W1, b1);
    colstats_k<1><<<dim3(H1_ / 32, NSPLIT), 256>>>(nullptr);
    colfinish_k<<<(H1_ + 255) / 256, 256>>>(H1_, g1, bb1);
    bn_apply_k<1><<<2048, 256>>>(nullptr);

    // layer 2: Linear -> tanh -> BN
    gemm_k<1><<<dim3(H2_ / 128, NTOK / 128), 256>>>(W2, b2);
    colstats_k<2><<<dim3(H2_ / 32, NSPLIT), 256>>>(nullptr);
    colfinish_k<<<(H2_ + 255) / 256, 256>>>(H2_, g2, bb2);
    bn_apply_k<2><<<2048, 256>>>(nullptr);

    // NONA: sim matrix + top-64 softmax aggregation
    rowsq_k<<<NTOK / 8, 256>>>();
    gemm_k<2><<<dim3(NTOK / 128, NTOK / 128), 256>>>(nullptr, nullptr);
    topk_k<<<NTOK, 256>>>(y_n, out);
}

// round 2
// speedup vs baseline: 1.3913x; 1.3913x over previous
#include <cuda_runtime.h>
#include <math.h>

// Problem constants (fixed by the reference).
constexpr int NTOK = 8192;   // N
constexpr int D_   = 512;
constexpr int H1_  = 1024;
constexpr int H2_  = 512;
constexpr int NC_  = 10;     // classes
constexpr int NSPLIT = 32;   // row splits for column stats

// ---------------- device scratch ---------------------------------------------------------
__device__ float g_xn[(size_t)NTOK * D_];          // 16 MB  normalized input
__device__ float g_h1[(size_t)NTOK * H1_];         // 32 MB  layer-1 activations (in-place BN)
__device__ float g_f [(size_t)NTOK * H2_];         // 16 MB  final features (in-place BN)
__device__ float g_S [(size_t)NTOK * NTOK];        // 268 MB similarity matrix
__device__ float g_sqn[NTOK];                      // row squared norms of f
__device__ float g_psum[NSPLIT * H1_];             // column-stat partials (max width H1)
__device__ float g_psq [NSPLIT * H1_];
__device__ float g_scale[H1_];                     // BN affine: y = x*scale + shift
__device__ float g_shift[H1_];

// ---------------- column stats: partial sums per (col, row-split) ----------------------
template <int STAGE>
__global__ __launch_bounds__(256) void colstats_k(const float* __restrict__ ext) {
    constexpr int NC = (STAGE == 0) ? D_ : (STAGE == 1 ? H1_ : H2_);
    const float* __restrict__ X = (STAGE == 0) ? ext : (STAGE == 1 ? g_h1 : g_f);
    const int lane = threadIdx.x & 31;
    const int warp = threadIdx.x >> 5;          // 0..7
    const int col  = blockIdx.x * 32 + lane;
    constexpr int RPS = NTOK / NSPLIT;          // 256 rows per split
    const int r0 = blockIdx.y * RPS;

    float s = 0.f, q = 0.f;
    for (int r = warp; r < RPS; r += 8) {
        float v = X[(size_t)(r0 + r) * NC + col];
        s += v;
        q += v * v;
    }
    __shared__ float shs[8][32];
    __shared__ float shq[8][32];
    shs[warp][lane] = s;
    shq[warp][lane] = q;
    __syncthreads();
    if (warp == 0) {
        float ts = 0.f, tq = 0.f;
#pragma unroll
        for (int w = 0; w < 8; w++) { ts += shs[w][lane]; tq += shq[w][lane]; }
        g_psum[blockIdx.y * NC + col] = ts;
        g_psq [blockIdx.y * NC + col] = tq;
    }
}

// ---------------- finalize stats -> scale/shift (double precision combine) -------------
__global__ void colfinish_k(int ncols, const float* __restrict__ g, const float* __restrict__ b) {
    int col = blockIdx.x * 256 + threadIdx.x;
    if (col >= ncols) return;
    double s = 0.0, q = 0.0;
    for (int p = 0; p < NSPLIT; p++) {
        s += (double)g_psum[p * ncols + col];
        q += (double)g_psq [p * ncols + col];
    }
    double mu  = s / (double)NTOK;
    double var = q / (double)NTOK - mu * mu;        // biased variance (matches reference)
    double sc  = (double)g[col] / sqrt(var + 1e-5);
    g_scale[col] = (float)sc;
    g_shift[col] = (float)((double)b[col] - mu * sc);
}

// ---------------- apply BN affine elementwise (float4) ---------------------------------
template <int STAGE>
__global__ __launch_bounds__(256) void bn_apply_k(const float* __restrict__ ext) {
    constexpr int NC = (STAGE == 0) ? D_ : (STAGE == 1 ? H1_ : H2_);
    const float* __restrict__ in = (STAGE == 0) ? ext : (STAGE == 1 ? g_h1 : g_f);
    float* __restrict__ outp     = (STAGE == 0) ? g_xn : (STAGE == 1 ? g_h1 : g_f);
    constexpr int TOT4 = NTOK * NC / 4;
    for (int i = blockIdx.x * blockDim.x + threadIdx.x; i < TOT4; i += gridDim.x * blockDim.x) {
        float4 v = reinterpret_cast<const float4*>(in)[i];
        int col = (i * 4) & (NC - 1);                 // NC is a power of 2
        v.x = fmaf(v.x, g_scale[col + 0], g_shift[col + 0]);
        v.y = fmaf(v.y, g_scale[col + 1], g_shift[col + 1]);
        v.z = fmaf(v.z, g_scale[col + 2], g_shift[col + 2]);
        v.w = fmaf(v.w, g_scale[col + 3], g_shift[col + 3]);
        reinterpret_cast<float4*>(outp)[i] = v;
    }
}

// ---------------- row squared norms of f ------------------------------------------------
__global__ __launch_bounds__(256) void rowsq_k() {
    int row  = blockIdx.x * 8 + (threadIdx.x >> 5);
    int lane = threadIdx.x & 31;
    float s = 0.f;
#pragma unroll
    for (int k = lane; k < H2_; k += 32) {
        float v = g_f[(size_t)row * H2_ + k];
        s = fmaf(v, v, s);
    }
#pragma unroll
    for (int o = 16; o; o >>= 1) s += __shfl_down_sync(0xffffffffu, s, o);
    if (!lane) g_sqn[row] = s;
}

// ---------------- tiled SGEMM (NT), double-buffered: C[i,j] = op(dot(A_i, B_j)) ---------
// MODE 0: A=g_xn [8192,512],  B=W1 [1024,512],  C=g_h1 = tanh(dot+b1)
// MODE 1: A=g_h1 [8192,1024], B=W2 [512,1024],  C=g_f  = tanh(dot+b2)
// MODE 2: A=B=g_f [8192,512], C=g_S = -dist (diag -inf); SYMMETRIC: upper-tri blocks only
template <int MODE>
__global__ __launch_bounds__(256, 2) void gemm_k(const float* __restrict__ Bext,
                                                 const float* __restrict__ bias) {
    constexpr int N = (MODE == 0) ? H1_ : (MODE == 1 ? H2_ : NTOK);
    constexpr int K = (MODE == 1) ? H1_ : D_;
    constexpr int NP = K / 16;                       // number of K panels
    const float* __restrict__ A = (MODE == 0) ? g_xn : (MODE == 1 ? g_h1 : g_f);
    const float* __restrict__ B = (MODE == 2) ? g_f : Bext;
    float* __restrict__ C       = (MODE == 0) ? g_h1 : (MODE == 1 ? g_f : g_S);

    int bx, by;
    if constexpr (MODE == 2) {
        // map linear block id -> (by, bx) with bx >= by (upper triangle incl. diag)
        int t = blockIdx.x;
        int a = (int)((sqrtf(8.f * (float)t + 1.f) - 1.f) * 0.5f);
        while ((a + 1) * (a + 2) / 2 <= t) ++a;
        while (a * (a + 1) / 2 > t) --a;
        bx = a;
        by = t - a * (a + 1) / 2;
    } else {
        bx = blockIdx.x; by = blockIdx.y;
    }

    __shared__ float As[2][16][132];   // 132 pad: rows 16B-aligned (132*4=528), conflict-lite
    __shared__ float Bs[2][16][132];

    const int tid  = threadIdx.x;
    const int brow = by * 128;
    const int bcol = bx * 128;
    const int tr   = (tid >> 4) << 3;      // 0..120
    const int tc   = (tid & 15) << 3;      // 0..120
    const int lr   = tid >> 2;             // 0..63
    const int lc   = (tid & 3) << 2;       // 0,4,8,12

    const float* Ap0 = A + (size_t)(brow + lr)      * K + lc;
    const float* Ap1 = A + (size_t)(brow + lr + 64) * K + lc;
    const float* Bp0 = B + (size_t)(bcol + lr)      * K + lc;
    const float* Bp1 = B + (size_t)(bcol + lr + 64) * K + lc;

    float acc[8][8] = {};

    // preload panel 0
    {
        float4 va0 = *reinterpret_cast<const float4*>(Ap0);
        float4 va1 = *reinterpret_cast<const float4*>(Ap1);
        float4 vb0 = *reinterpret_cast<const float4*>(Bp0);
        float4 vb1 = *reinterpret_cast<const float4*>(Bp1);
        As[0][lc+0][lr]    = va0.x; As[0][lc+1][lr]    = va0.y; As[0][lc+2][lr]    = va0.z; As[0][lc+3][lr]    = va0.w;
        As[0][lc+0][lr+64] = va1.x; As[0][lc+1][lr+64] = va1.y; As[0][lc+2][lr+64] = va1.z; As[0][lc+3][lr+64] = va1.w;
        Bs[0][lc+0][lr]    = vb0.x; Bs[0][lc+1][lr]    = vb0.y; Bs[0][lc+2][lr]    = vb0.z; Bs[0][lc+3][lr]    = vb0.w;
        Bs[0][lc+0][lr+64] = vb1.x; Bs[0][lc+1][lr+64] = vb1.y; Bs[0][lc+2][lr+64] = vb1.z; Bs[0][lc+3][lr+64] = vb1.w;
    }
    __syncthreads();

    int buf = 0;
#pragma unroll 1
    for (int p = 0; p < NP; p++) {
        float4 va0, va1, vb0, vb1;
        const bool more = (p + 1 < NP);
        if (more) {
            int off = (p + 1) * 16;
            va0 = *reinterpret_cast<const float4*>(Ap0 + off);
            va1 = *reinterpret_cast<const float4*>(Ap1 + off);
            vb0 = *reinterpret_cast<const float4*>(Bp0 + off);
            vb1 = *reinterpret_cast<const float4*>(Bp1 + off);
        }
#pragma unroll
        for (int kk = 0; kk < 16; kk++) {
            float4 a0 = *reinterpret_cast<const float4*>(&As[buf][kk][tr]);
            float4 a1 = *reinterpret_cast<const float4*>(&As[buf][kk][tr + 4]);
            float4 b0 = *reinterpret_cast<const float4*>(&Bs[buf][kk][tc]);
            float4 b1 = *reinterpret_cast<const float4*>(&Bs[buf][kk][tc + 4]);
            float ar[8] = {a0.x, a0.y, a0.z, a0.w, a1.x, a1.y, a1.z, a1.w};
            float br[8] = {b0.x, b0.y, b0.z, b0.w, b1.x, b1.y, b1.z, b1.w};
#pragma unroll
            for (int i = 0; i < 8; i++)
#pragma unroll
                for (int j = 0; j < 8; j++)
                    acc[i][j] = fmaf(ar[i], br[j], acc[i][j]);
        }
        if (more) {
            int nb = buf ^ 1;
            As[nb][lc+0][lr]    = va0.x; As[nb][lc+1][lr]    = va0.y; As[nb][lc+2][lr]    = va0.z; As[nb][lc+3][lr]    = va0.w;
            As[nb][lc+0][lr+64] = va1.x; As[nb][lc+1][lr+64] = va1.y; As[nb][lc+2][lr+64] = va1.z; As[nb][lc+3][lr+64] = va1.w;
            Bs[nb][lc+0][lr]    = vb0.x; Bs[nb][lc+1][lr]    = vb0.y; Bs[nb][lc+2][lr]    = vb0.z; Bs[nb][lc+3][lr]    = vb0.w;
            Bs[nb][lc+0][lr+64] = vb1.x; Bs[nb][lc+1][lr+64] = vb1.y; Bs[nb][lc+2][lr+64] = vb1.z; Bs[nb][lc+3][lr+64] = vb1.w;
            __syncthreads();
            buf = nb;
        }
    }

    if constexpr (MODE == 2) {
        float sqj[8];
#pragma unroll
        for (int j = 0; j < 8; j++) sqj[j] = g_sqn[bcol + tc + j];
        const bool mirror = (bx != by);
#pragma unroll
        for (int i = 0; i < 8; i++) {
            int gi = brow + tr + i;
            float sqi = g_sqn[gi];
#pragma unroll
            for (int j = 0; j < 8; j++) {
                int gj = bcol + tc + j;
                float d2 = fmaxf(sqi + sqj[j] - 2.f * acc[i][j], 0.f);
                float s  = (d2 > 1e-9f) ? -sqrtf(d2) : 0.f;   // matches reference guard
                if (gi == gj) s = -INFINITY;                  // self-neighbor mask
                C[(size_t)gi * NTOK + gj] = s;
                if (mirror) C[(size_t)gj * NTOK + gi] = s;    // symmetric twin
            }
        }
    } else {
#pragma unroll
        for (int i = 0; i < 8; i++) {
            int gi = brow + tr + i;
#pragma unroll
            for (int j = 0; j < 8; j++) {
                int gj = bcol + tc + j;
                C[(size_t)gi * N + gj] = tanhf(acc[i][j] + bias[gj]);
            }
        }
    }
}

// ---------------- per-row top-64 + softmax + one-hot scatter ----------------------------
__global__ __launch_bounds__(256) void topk_k(const int* __restrict__ yn, float* __restrict__ out) {
    const int row  = blockIdx.x;
    const float* __restrict__ srow = g_S + (size_t)row * NTOK;
    const int tid  = threadIdx.x;
    const int lane = tid & 31;
    const int warp = tid >> 5;

    float v[32];
#pragma unroll
    for (int k = 0; k < 32; k++) v[k] = srow[tid + (k << 8)];

    float lm = -INFINITY; int li = 0;
#pragma unroll
    for (int k = 0; k < 32; k++) if (v[k] > lm) { lm = v[k]; li = k; }

    __shared__ float swv[8];
    __shared__ int   swi[8];
    __shared__ int   sbroad;
    __shared__ float wval[64];
    __shared__ int   widx[64];

    for (int it = 0; it < 64; it++) {
        float bv = lm;
        int   bi = tid + (li << 8);
#pragma unroll
        for (int o = 16; o; o >>= 1) {
            float ov = __shfl_down_sync(0xffffffffu, bv, o);
            int   oi = __shfl_down_sync(0xffffffffu, bi, o);
            if (ov > bv || (ov == bv && oi < bi)) { bv = ov; bi = oi; }   // tie -> lower index
        }
        if (!lane) { swv[warp] = bv; swi[warp] = bi; }
        __syncthreads();
        if (!tid) {
            float wv = swv[0]; int wi = swi[0];
#pragma unroll
            for (int w = 1; w < 8; w++)
                if (swv[w] > wv || (swv[w] == wv && swi[w] < wi)) { wv = swv[w]; wi = swi[w]; }
            wval[it] = wv; widx[it] = wi; sbroad = wi;
        }
        __syncthreads();
        int wi = sbroad;
        if ((wi & 255) == tid) {          // owner removes winner, recomputes local max
            v[wi >> 8] = -INFINITY;
            lm = -INFINITY; li = 0;
#pragma unroll
            for (int k = 0; k < 32; k++) if (v[k] > lm) { lm = v[k]; li = k; }
        }
    }
    __syncthreads();

    __shared__ float earr[64];
    __shared__ int   larr[64];
    if (tid < 64) {
        earr[tid] = expf(wval[tid] - wval[0]);   // wval[0] is the row max
        larr[tid] = yn[widx[tid]];
    }
    __syncthreads();

    __shared__ float bins[NC_];
    __shared__ float tot;
    if (!tid) {                                   // serial: deterministic accumulation
        float bb[NC_];
#pragma unroll
        for (int c = 0; c < NC_; c++) bb[c] = 0.f;
        float t = 0.f;
        for (int k = 0; k < 64; k++) { t += earr[k]; bb[larr[k]] += earr[k]; }
        tot = t;
#pragma unroll
        for (int c = 0; c < NC_; c++) bins[c] = bb[c];
    }
    __syncthreads();
    if (tid < NC_) {
        float p = bins[tid] / tot;
        out[(size_t)row * NC_ + tid] = fminf(fmaxf(p, 0.f), 1.f);
    }
}

// ---------------- launcher --------------------------------------------------------------
extern "C" void kernel_launch(void* const* d_in, const int* in_sizes, int n_in,
                              void* d_out, int out_size) {
    (void)in_sizes; (void)n_in; (void)out_size;
    const float* x     = (const float*)d_in[0];
    // d_in[1] is x_n == x elementwise (reference guarantees it) -> features computed once
    const int*   y_n   = (const int*)  d_in[2];
    const float* ibn_g = (const float*)d_in[3];
    const float* ibn_b = (const float*)d_in[4];
    const float* W1    = (const float*)d_in[5];
    const float* b1    = (const float*)d_in[6];
    const float* g1    = (const float*)d_in[7];
    const float* bb1   = (const float*)d_in[8];
    const float* W2    = (const float*)d_in[9];
    const float* b2    = (const float*)d_in[10];
    const float* g2    = (const float*)d_in[11];
    const float* bb2   = (const float*)d_in[12];
    float* out = (float*)d_out;

    // input BN
    colstats_k<0><<<dim3(D_ / 32, NSPLIT), 256>>>(x);
    colfinish_k<<<(D_ + 255) / 256, 256>>>(D_, ibn_g, ibn_b);
    bn_apply_k<0><<<2048, 256>>>(x);

    // layer 1: Linear -> tanh -> BN
    gemm_k<0><<<dim3(H1_ / 128, NTOK / 128), 256>>>(W1, b1);
    colstats_k<1><<<dim3(H1_ / 32, NSPLIT), 256>>>(nullptr);
    colfinish_k<<<(H1_ + 255) / 256, 256>>>(H1_, g1, bb1);
    bn_apply_k<1><<<2048, 256>>>(nullptr);

    // layer 2: Linear -> tanh -> BN
    gemm_k<1><<<dim3(H2_ / 128, NTOK / 128), 256>>>(W2, b2);
    colstats_k<2><<<dim3(H2_ / 32, NSPLIT), 256>>>(nullptr);
    colfinish_k<<<(H2_ + 255) / 256, 256>>>(H2_, g2, bb2);
    bn_apply_k<2><<<2048, 256>>>(nullptr);

    // NONA: sim matrix (symmetric, upper-triangle blocks) + top-64 softmax aggregation
    rowsq_k<<<NTOK / 8, 256>>>();
    constexpr int NBLK = NTOK / 128;                        // 64
    gemm_k<2><<<NBLK * (NBLK + 1) / 2, 256>>>(nullptr, nullptr);
    topk_k<<<NTOK, 256>>>(y_n, out);
}

// round 3
// speedup vs baseline: 1.5461x; 1.1113x over previous
#include <cuda_runtime.h>
#include <math.h>

// Problem constants (fixed by the reference).
constexpr int NTOK = 8192;   // N
constexpr int D_   = 512;
constexpr int H1_  = 1024;
constexpr int H2_  = 512;
constexpr int NC_  = 10;     // classes
constexpr int NSPLIT = 32;   // row splits for column stats

// ---------------- device scratch ---------------------------------------------------------
__device__ float g_xn[(size_t)NTOK * D_];          // 16 MB  normalized input
__device__ float g_h1[(size_t)NTOK * H1_];         // 32 MB  layer-1 activations (in-place BN)
__device__ float g_f [(size_t)NTOK * H2_];         // 16 MB  final features (in-place BN)
__device__ float g_S [(size_t)NTOK * NTOK];        // 268 MB similarity matrix
__device__ float g_sqn[NTOK];                      // row squared norms of f
__device__ float g_psum[NSPLIT * H1_];             // column-stat partials (max width H1)
__device__ float g_psq [NSPLIT * H1_];
__device__ float g_scale[H1_];                     // BN affine: y = x*scale + shift
__device__ float g_shift[H1_];

// ---------------- column stats: partial sums per (col, row-split) ----------------------
template <int STAGE>
__global__ __launch_bounds__(256) void colstats_k(const float* __restrict__ ext) {
    constexpr int NC = (STAGE == 0) ? D_ : (STAGE == 1 ? H1_ : H2_);
    const float* __restrict__ X = (STAGE == 0) ? ext : (STAGE == 1 ? g_h1 : g_f);
    const int lane = threadIdx.x & 31;
    const int warp = threadIdx.x >> 5;          // 0..7
    const int col  = blockIdx.x * 32 + lane;
    constexpr int RPS = NTOK / NSPLIT;          // 256 rows per split
    const int r0 = blockIdx.y * RPS;

    float s = 0.f, q = 0.f;
    for (int r = warp; r < RPS; r += 8) {
        float v = X[(size_t)(r0 + r) * NC + col];
        s += v;
        q += v * v;
    }
    __shared__ float shs[8][32];
    __shared__ float shq[8][32];
    shs[warp][lane] = s;
    shq[warp][lane] = q;
    __syncthreads();
    if (warp == 0) {
        float ts = 0.f, tq = 0.f;
#pragma unroll
        for (int w = 0; w < 8; w++) { ts += shs[w][lane]; tq += shq[w][lane]; }
        g_psum[blockIdx.y * NC + col] = ts;
        g_psq [blockIdx.y * NC + col] = tq;
    }
}

// ---------------- finalize stats -> scale/shift (double precision combine) -------------
__global__ void colfinish_k(int ncols, const float* __restrict__ g, const float* __restrict__ b) {
    int col = blockIdx.x * 256 + threadIdx.x;
    if (col >= ncols) return;
    double s = 0.0, q = 0.0;
    for (int p = 0; p < NSPLIT; p++) {
        s += (double)g_psum[p * ncols + col];
        q += (double)g_psq [p * ncols + col];
    }
    double mu  = s / (double)NTOK;
    double var = q / (double)NTOK - mu * mu;        // biased variance (matches reference)
    double sc  = (double)g[col] / sqrt(var + 1e-5);
    g_scale[col] = (float)sc;
    g_shift[col] = (float)((double)b[col] - mu * sc);
}

// ---------------- apply BN affine elementwise (float4) ---------------------------------
template <int STAGE>
__global__ __launch_bounds__(256) void bn_apply_k(const float* __restrict__ ext) {
    constexpr int NC = (STAGE == 0) ? D_ : (STAGE == 1 ? H1_ : H2_);
    const float* __restrict__ in = (STAGE == 0) ? ext : (STAGE == 1 ? g_h1 : g_f);
    float* __restrict__ outp     = (STAGE == 0) ? g_xn : (STAGE == 1 ? g_h1 : g_f);
    constexpr int TOT4 = NTOK * NC / 4;
    for (int i = blockIdx.x * blockDim.x + threadIdx.x; i < TOT4; i += gridDim.x * blockDim.x) {
        float4 v = reinterpret_cast<const float4*>(in)[i];
        int col = (i * 4) & (NC - 1);                 // NC is a power of 2
        v.x = fmaf(v.x, g_scale[col + 0], g_shift[col + 0]);
        v.y = fmaf(v.y, g_scale[col + 1], g_shift[col + 1]);
        v.z = fmaf(v.z, g_scale[col + 2], g_shift[col + 2]);
        v.w = fmaf(v.w, g_scale[col + 3], g_shift[col + 3]);
        reinterpret_cast<float4*>(outp)[i] = v;
    }
}

// ---------------- row squared norms of f ------------------------------------------------
__global__ __launch_bounds__(256) void rowsq_k() {
    int row  = blockIdx.x * 8 + (threadIdx.x >> 5);
    int lane = threadIdx.x & 31;
    float s = 0.f;
#pragma unroll
    for (int k = lane; k < H2_; k += 32) {
        float v = g_f[(size_t)row * H2_ + k];
        s = fmaf(v, v, s);
    }
#pragma unroll
    for (int o = 16; o; o >>= 1) s += __shfl_down_sync(0xffffffffu, s, o);
    if (!lane) g_sqn[row] = s;
}

// ---------------- tiled SGEMM (NT), double-buffered, conflict-free fragments ------------
// Block 128x128, 8 warps as 4(row) x 2(col); warp tile 32x64.
// Lane (ty = lane>>3, tx = lane&7); thread tile 8x8 = 2x2 quads of 4x4:
//   rows {wy*32+ty*4 .. +3} and {+16}, cols {wx*64+tx*4 .. +3} and {+32}.
// MODE 0: A=g_xn [8192,512],  B=W1 [1024,512],  C=g_h1 = tanh(dot+b1)
// MODE 1: A=g_h1 [8192,1024], B=W2 [512,1024],  C=g_f  = tanh(dot+b2)
// MODE 2: A=B=g_f [8192,512], C=g_S = -dist (diag -inf); upper-tri blocks, mirrored
template <int MODE>
__global__ __launch_bounds__(256, 2) void gemm_k(const float* __restrict__ Bext,
                                                 const float* __restrict__ bias) {
    constexpr int N = (MODE == 0) ? H1_ : (MODE == 1 ? H2_ : NTOK);
    constexpr int K = (MODE == 1) ? H1_ : D_;
    constexpr int NP = K / 16;                       // number of K panels
    const float* __restrict__ A = (MODE == 0) ? g_xn : (MODE == 1 ? g_h1 : g_f);
    const float* __restrict__ B = (MODE == 2) ? g_f : Bext;
    float* __restrict__ C       = (MODE == 0) ? g_h1 : (MODE == 1 ? g_f : g_S);

    int bx, by;
    if constexpr (MODE == 2) {
        // map linear block id -> (by, bx) with bx >= by (upper triangle incl. diag)
        int t = blockIdx.x;
        int a = (int)((sqrtf(8.f * (float)t + 1.f) - 1.f) * 0.5f);
        while ((a + 1) * (a + 2) / 2 <= t) ++a;
        while (a * (a + 1) / 2 > t) --a;
        bx = a;
        by = t - a * (a + 1) / 2;
    } else {
        bx = blockIdx.x; by = blockIdx.y;
    }

    __shared__ float As[2][16][132];
    __shared__ float Bs[2][16][132];

    const int tid  = threadIdx.x;
    const int lane = tid & 31;
    const int wid  = tid >> 5;            // 0..7
    const int wy   = wid >> 1;            // 0..3  (32-row strip)
    const int wx   = wid & 1;             // 0..1  (64-col strip)
    const int ty   = lane >> 3;           // 0..3
    const int tx   = lane & 7;            // 0..7
    const int fr   = wy * 32 + ty * 4;    // fragment row offset in tile (plus +16 twin)
    const int fc   = wx * 64 + tx * 4;    // fragment col offset in tile (plus +32 twin)

    const int brow = by * 128;
    const int bcol = bx * 128;
    const int lr   = tid >> 2;             // 0..63   (smem fill)
    const int lc   = (tid & 3) << 2;       // 0,4,8,12

    const float* Ap0 = A + (size_t)(brow + lr)      * K + lc;
    const float* Ap1 = A + (size_t)(brow + lr + 64) * K + lc;
    const float* Bp0 = B + (size_t)(bcol + lr)      * K + lc;
    const float* Bp1 = B + (size_t)(bcol + lr + 64) * K + lc;

    float acc[8][8] = {};

    // preload panel 0
    {
        float4 va0 = *reinterpret_cast<const float4*>(Ap0);
        float4 va1 = *reinterpret_cast<const float4*>(Ap1);
        float4 vb0 = *reinterpret_cast<const float4*>(Bp0);
        float4 vb1 = *reinterpret_cast<const float4*>(Bp1);
        As[0][lc+0][lr]    = va0.x; As[0][lc+1][lr]    = va0.y; As[0][lc+2][lr]    = va0.z; As[0][lc+3][lr]    = va0.w;
        As[0][lc+0][lr+64] = va1.x; As[0][lc+1][lr+64] = va1.y; As[0][lc+2][lr+64] = va1.z; As[0][lc+3][lr+64] = va1.w;
        Bs[0][lc+0][lr]    = vb0.x; Bs[0][lc+1][lr]    = vb0.y; Bs[0][lc+2][lr]    = vb0.z; Bs[0][lc+3][lr]    = vb0.w;
        Bs[0][lc+0][lr+64] = vb1.x; Bs[0][lc+1][lr+64] = vb1.y; Bs[0][lc+2][lr+64] = vb1.z; Bs[0][lc+3][lr+64] = vb1.w;
    }
    __syncthreads();

    int buf = 0;
#pragma unroll 1
    for (int p = 0; p < NP; p++) {
        float4 va0, va1, vb0, vb1;
        const bool more = (p + 1 < NP);
        if (more) {
            int off = (p + 1) * 16;
            va0 = *reinterpret_cast<const float4*>(Ap0 + off);
            va1 = *reinterpret_cast<const float4*>(Ap1 + off);
            vb0 = *reinterpret_cast<const float4*>(Bp0 + off);
            vb1 = *reinterpret_cast<const float4*>(Bp1 + off);
        }
#pragma unroll
        for (int kk = 0; kk < 16; kk++) {
            float4 a0 = *reinterpret_cast<const float4*>(&As[buf][kk][fr]);
            float4 a1 = *reinterpret_cast<const float4*>(&As[buf][kk][fr + 16]);
            float4 b0 = *reinterpret_cast<const float4*>(&Bs[buf][kk][fc]);
            float4 b1 = *reinterpret_cast<const float4*>(&Bs[buf][kk][fc + 32]);
            float ar[8] = {a0.x, a0.y, a0.z, a0.w, a1.x, a1.y, a1.z, a1.w};
            float br[8] = {b0.x, b0.y, b0.z, b0.w, b1.x, b1.y, b1.z, b1.w};
#pragma unroll
            for (int i = 0; i < 8; i++)
#pragma unroll
                for (int j = 0; j < 8; j++)
                    acc[i][j] = fmaf(ar[i], br[j], acc[i][j]);
        }
        if (more) {
            int nb = buf ^ 1;
            As[nb][lc+0][lr]    = va0.x; As[nb][lc+1][lr]    = va0.y; As[nb][lc+2][lr]    = va0.z; As[nb][lc+3][lr]    = va0.w;
            As[nb][lc+0][lr+64] = va1.x; As[nb][lc+1][lr+64] = va1.y; As[nb][lc+2][lr+64] = va1.z; As[nb][lc+3][lr+64] = va1.w;
            Bs[nb][lc+0][lr]    = vb0.x; Bs[nb][lc+1][lr]    = vb0.y; Bs[nb][lc+2][lr]    = vb0.z; Bs[nb][lc+3][lr]    = vb0.w;
            Bs[nb][lc+0][lr+64] = vb1.x; Bs[nb][lc+1][lr+64] = vb1.y; Bs[nb][lc+2][lr+64] = vb1.z; Bs[nb][lc+3][lr+64] = vb1.w;
            __syncthreads();
            buf = nb;
        }
    }

    if constexpr (MODE == 2) {
        const bool mirror = (bx != by);
        float sv[8][8];
        int gr[2] = {brow + fr, brow + fr + 16};
        int gc[2] = {bcol + fc, bcol + fc + 32};
        float sqi[2][4], sqj[2][4];
#pragma unroll
        for (int q = 0; q < 2; q++)
#pragma unroll
            for (int u = 0; u < 4; u++) {
                sqi[q][u] = g_sqn[gr[q] + u];
                sqj[q][u] = g_sqn[gc[q] + u];
            }
#pragma unroll
        for (int qi = 0; qi < 2; qi++)
#pragma unroll
        for (int u = 0; u < 4; u++) {
            int gi = gr[qi] + u;
#pragma unroll
            for (int qj = 0; qj < 2; qj++)
#pragma unroll
            for (int v = 0; v < 4; v++) {
                int gj = gc[qj] + v;
                float d2 = fmaxf(sqi[qi][u] + sqj[qj][v] - 2.f * acc[qi*4+u][qj*4+v], 0.f);
                float s  = (d2 > 1e-9f) ? -sqrtf(d2) : 0.f;   // matches reference guard
                if (gi == gj) s = -INFINITY;                  // self-neighbor mask
                sv[qi*4+u][qj*4+v] = s;
            }
        }
        // direct stores: 4 consecutive cols per float4
#pragma unroll
        for (int qi = 0; qi < 2; qi++)
#pragma unroll
        for (int u = 0; u < 4; u++) {
            size_t rowoff = (size_t)(gr[qi] + u) * NTOK;
#pragma unroll
            for (int qj = 0; qj < 2; qj++) {
                float4 w = {sv[qi*4+u][qj*4+0], sv[qi*4+u][qj*4+1],
                            sv[qi*4+u][qj*4+2], sv[qi*4+u][qj*4+3]};
                *reinterpret_cast<float4*>(&C[rowoff + gc[qj]]) = w;
            }
        }
        // mirrored stores: register quad transpose -> coalesced float4
        if (mirror) {
#pragma unroll
            for (int qj = 0; qj < 2; qj++)
#pragma unroll
            for (int v = 0; v < 4; v++) {
                size_t rowoff = (size_t)(gc[qj] + v) * NTOK;
#pragma unroll
                for (int qi = 0; qi < 2; qi++) {
                    float4 w = {sv[qi*4+0][qj*4+v], sv[qi*4+1][qj*4+v],
                                sv[qi*4+2][qj*4+v], sv[qi*4+3][qj*4+v]};
                    *reinterpret_cast<float4*>(&C[rowoff + gr[qi]]) = w;
                }
            }
        }
    } else {
        int gr[2] = {brow + fr, brow + fr + 16};
        int gc[2] = {bcol + fc, bcol + fc + 32};
        float4 bv[2];
#pragma unroll
        for (int qj = 0; qj < 2; qj++)
            bv[qj] = *reinterpret_cast<const float4*>(&bias[gc[qj]]);
#pragma unroll
        for (int qi = 0; qi < 2; qi++)
#pragma unroll
        for (int u = 0; u < 4; u++) {
            size_t rowoff = (size_t)(gr[qi] + u) * N;
#pragma unroll
            for (int qj = 0; qj < 2; qj++) {
                float4 w;
                w.x = tanhf(acc[qi*4+u][qj*4+0] + bv[qj].x);
                w.y = tanhf(acc[qi*4+u][qj*4+1] + bv[qj].y);
                w.z = tanhf(acc[qi*4+u][qj*4+2] + bv[qj].z);
                w.w = tanhf(acc[qi*4+u][qj*4+3] + bv[qj].w);
                *reinterpret_cast<float4*>(&C[rowoff + gc[qj]]) = w;
            }
        }
    }
}

// ---------------- per-row top-64 + softmax + one-hot scatter ----------------------------
__global__ __launch_bounds__(256) void topk_k(const int* __restrict__ yn, float* __restrict__ out) {
    const int row  = blockIdx.x;
    const float* __restrict__ srow = g_S + (size_t)row * NTOK;
    const int tid  = threadIdx.x;
    const int lane = tid & 31;
    const int warp = tid >> 5;

    float v[32];
#pragma unroll
    for (int k = 0; k < 32; k++) v[k] = srow[tid + (k << 8)];

    float lm = -INFINITY; int li = 0;
#pragma unroll
    for (int k = 0; k < 32; k++) if (v[k] > lm) { lm = v[k]; li = k; }

    __shared__ float swv[8];
    __shared__ int   swi[8];
    __shared__ int   sbroad;
    __shared__ float wval[64];
    __shared__ int   widx[64];

    for (int it = 0; it < 64; it++) {
        float bv = lm;
        int   bi = tid + (li << 8);
#pragma unroll
        for (int o = 16; o; o >>= 1) {
            float ov = __shfl_down_sync(0xffffffffu, bv, o);
            int   oi = __shfl_down_sync(0xffffffffu, bi, o);
            if (ov > bv || (ov == bv && oi < bi)) { bv = ov; bi = oi; }   // tie -> lower index
        }
        if (!lane) { swv[warp] = bv; swi[warp] = bi; }
        __syncthreads();
        if (!tid) {
            float wv = swv[0]; int wi = swi[0];
#pragma unroll
            for (int w = 1; w < 8; w++)
                if (swv[w] > wv || (swv[w] == wv && swi[w] < wi)) { wv = swv[w]; wi = swi[w]; }
            wval[it] = wv; widx[it] = wi; sbroad = wi;
        }
        __syncthreads();
        int wi = sbroad;
        if ((wi & 255) == tid) {          // owner removes winner, recomputes local max
            v[wi >> 8] = -INFINITY;
            lm = -INFINITY; li = 0;
#pragma unroll
            for (int k = 0; k < 32; k++) if (v[k] > lm) { lm = v[k]; li = k; }
        }
    }
    __syncthreads();

    __shared__ float earr[64];
    __shared__ int   larr[64];
    if (tid < 64) {
        earr[tid] = expf(wval[tid] - wval[0]);   // wval[0] is the row max
        larr[tid] = yn[widx[tid]];
    }
    __syncthreads();

    __shared__ float bins[NC_];
    __shared__ float tot;
    if (!tid) {                                   // serial: deterministic accumulation
        float bb[NC_];
#pragma unroll
        for (int c = 0; c < NC_; c++) bb[c] = 0.f;
        float t = 0.f;
        for (int k = 0; k < 64; k++) { t += earr[k]; bb[larr[k]] += earr[k]; }
        tot = t;
#pragma unroll
        for (int c = 0; c < NC_; c++) bins[c] = bb[c];
    }
    __syncthreads();
    if (tid < NC_) {
        float p = bins[tid] / tot;
        out[(size_t)row * NC_ + tid] = fminf(fmaxf(p, 0.f), 1.f);
    }
}

// ---------------- launcher --------------------------------------------------------------
extern "C" void kernel_launch(void* const* d_in, const int* in_sizes, int n_in,
                              void* d_out, int out_size) {
    (void)in_sizes; (void)n_in; (void)out_size;
    const float* x     = (const float*)d_in[0];
    // d_in[1] is x_n == x elementwise (reference guarantees it) -> features computed once
    const int*   y_n   = (const int*)  d_in[2];
    const float* ibn_g = (const float*)d_in[3];
    const float* ibn_b = (const float*)d_in[4];
    const float* W1    = (const float*)d_in[5];
    const float* b1    = (const float*)d_in[6];
    const float* g1    = (const float*)d_in[7];
    const float* bb1   = (const float*)d_in[8];
    const float* W2    = (const float*)d_in[9];
    const float* b2    = (const float*)d_in[10];
    const float* g2    = (const float*)d_in[11];
    const float* bb2   = (const float*)d_in[12];
    float* out = (float*)d_out;

    // input BN
    colstats_k<0><<<dim3(D_ / 32, NSPLIT), 256>>>(x);
    colfinish_k<<<(D_ + 255) / 256, 256>>>(D_, ibn_g, ibn_b);
    bn_apply_k<0><<<2048, 256>>>(x);

    // layer 1: Linear -> tanh -> BN
    gemm_k<0><<<dim3(H1_ / 128, NTOK / 128), 256>>>(W1, b1);
    colstats_k<1><<<dim3(H1_ / 32, NSPLIT), 256>>>(nullptr);
    colfinish_k<<<(H1_ + 255) / 256, 256>>>(H1_, g1, bb1);
    bn_apply_k<1><<<2048, 256>>>(nullptr);

    // layer 2: Linear -> tanh -> BN
    gemm_k<1><<<dim3(H2_ / 128, NTOK / 128), 256>>>(W2, b2);
    colstats_k<2><<<dim3(H2_ / 32, NSPLIT), 256>>>(nullptr);
    colfinish_k<<<(H2_ + 255) / 256, 256>>>(H2_, g2, bb2);
    bn_apply_k<2><<<2048, 256>>>(nullptr);

    // NONA: sim matrix (symmetric, upper-triangle blocks) + top-64 softmax aggregation
    rowsq_k<<<NTOK / 8, 256>>>();
    constexpr int NBLK = NTOK / 128;                        // 64
    gemm_k<2><<<NBLK * (NBLK + 1) / 2, 256>>>(nullptr, nullptr);
    topk_k<<<NTOK, 256>>>(y_n, out);
}

// round 6
// speedup vs baseline: 1.7414x; 1.1263x over previous
#include <cuda_runtime.h>
#include <math.h>
#include <stdint.h>

// Problem constants (fixed by the reference).
constexpr int NTOK = 8192;   // N
constexpr int D_   = 512;
constexpr int H1_  = 1024;
constexpr int H2_  = 512;
constexpr int NC_  = 10;     // classes
constexpr int NSPLIT = 32;   // row splits for column stats

// ---------------- device scratch ---------------------------------------------------------
__device__ float g_xn[(size_t)NTOK * D_];          // 16 MB  normalized input
__device__ float g_h1[(size_t)NTOK * H1_];         // 32 MB  layer-1 activations (in-place BN)
__device__ float g_f [(size_t)NTOK * H2_];         // 16 MB  final features (in-place BN)
__device__ float g_S [(size_t)NTOK * NTOK];        // 268 MB similarity matrix
__device__ float g_sqn[NTOK];                      // row squared norms of f
__device__ float g_psum[NSPLIT * H1_];
__device__ float g_psq [NSPLIT * H1_];
__device__ float g_scale[H1_];
__device__ float g_shift[H1_];

// ---------------- column stats ----------------------------------------------------------
template <int STAGE>
__global__ __launch_bounds__(256) void colstats_k(const float* __restrict__ ext) {
    constexpr int NC = (STAGE == 0) ? D_ : (STAGE == 1 ? H1_ : H2_);
    const float* __restrict__ X = (STAGE == 0) ? ext : (STAGE == 1 ? g_h1 : g_f);
    const int lane = threadIdx.x & 31;
    const int warp = threadIdx.x >> 5;
    const int col  = blockIdx.x * 32 + lane;
    constexpr int RPS = NTOK / NSPLIT;
    const int r0 = blockIdx.y * RPS;

    float s = 0.f, q = 0.f;
    for (int r = warp; r < RPS; r += 8) {
        float v = X[(size_t)(r0 + r) * NC + col];
        s += v;
        q += v * v;
    }
    __shared__ float shs[8][32];
    __shared__ float shq[8][32];
    shs[warp][lane] = s;
    shq[warp][lane] = q;
    __syncthreads();
    if (warp == 0) {
        float ts = 0.f, tq = 0.f;
#pragma unroll
        for (int w = 0; w < 8; w++) { ts += shs[w][lane]; tq += shq[w][lane]; }
        g_psum[blockIdx.y * NC + col] = ts;
        g_psq [blockIdx.y * NC + col] = tq;
    }
}

__global__ void colfinish_k(int ncols, const float* __restrict__ g, const float* __restrict__ b) {
    int col = blockIdx.x * 256 + threadIdx.x;
    if (col >= ncols) return;
    double s = 0.0, q = 0.0;
    for (int p = 0; p < NSPLIT; p++) {
        s += (double)g_psum[p * ncols + col];
        q += (double)g_psq [p * ncols + col];
    }
    double mu  = s / (double)NTOK;
    double var = q / (double)NTOK - mu * mu;
    double sc  = (double)g[col] / sqrt(var + 1e-5);
    g_scale[col] = (float)sc;
    g_shift[col] = (float)((double)b[col] - mu * sc);
}

template <int STAGE>
__global__ __launch_bounds__(256) void bn_apply_k(const float* __restrict__ ext) {
    constexpr int NC = (STAGE == 0) ? D_ : (STAGE == 1 ? H1_ : H2_);
    const float* __restrict__ in = (STAGE == 0) ? ext : (STAGE == 1 ? g_h1 : g_f);
    float* __restrict__ outp     = (STAGE == 0) ? g_xn : (STAGE == 1 ? g_h1 : g_f);
    constexpr int TOT4 = NTOK * NC / 4;
    for (int i = blockIdx.x * blockDim.x + threadIdx.x; i < TOT4; i += gridDim.x * blockDim.x) {
        float4 v = reinterpret_cast<const float4*>(in)[i];
        int col = (i * 4) & (NC - 1);
        v.x = fmaf(v.x, g_scale[col + 0], g_shift[col + 0]);
        v.y = fmaf(v.y, g_scale[col + 1], g_shift[col + 1]);
        v.z = fmaf(v.z, g_scale[col + 2], g_shift[col + 2]);
        v.w = fmaf(v.w, g_scale[col + 3], g_shift[col + 3]);
        reinterpret_cast<float4*>(outp)[i] = v;
    }
}

__global__ __launch_bounds__(256) void rowsq_k() {
    int row  = blockIdx.x * 8 + (threadIdx.x >> 5);
    int lane = threadIdx.x & 31;
    float s = 0.f;
#pragma unroll
    for (int k = lane; k < H2_; k += 32) {
        float v = g_f[(size_t)row * H2_ + k];
        s = fmaf(v, v, s);
    }
#pragma unroll
    for (int o = 16; o; o >>= 1) s += __shfl_down_sync(0xffffffffu, s, o);
    if (!lane) g_sqn[row] = s;
}

// ================= fp32 SIMT GEMM for feature layers (bit-matches round-3 run) ===========
// MODE 0: A=g_xn [8192,512],  B=W1 [1024,512],  C=g_h1 = tanh(dot+b1)
// MODE 1: A=g_h1 [8192,1024], B=W2 [512,1024],  C=g_f  = tanh(dot+b2)
template <int MODE>
__global__ __launch_bounds__(256, 2) void gemm_k(const float* __restrict__ Bext,
                                                 const float* __restrict__ bias) {
    constexpr int N = (MODE == 0) ? H1_ : H2_;
    constexpr int K = (MODE == 1) ? H1_ : D_;
    constexpr int NP = K / 16;
    const float* __restrict__ A = (MODE == 0) ? g_xn : g_h1;
    const float* __restrict__ B = Bext;
    float* __restrict__ C       = (MODE == 0) ? g_h1 : g_f;

    const int bx = blockIdx.x, by = blockIdx.y;

    __shared__ float As[2][16][132];
    __shared__ float Bs[2][16][132];

    const int tid  = threadIdx.x;
    const int lane = tid & 31;
    const int wid  = tid >> 5;
    const int wy   = wid >> 1;
    const int wx   = wid & 1;
    const int ty   = lane >> 3;
    const int tx   = lane & 7;
    const int fr   = wy * 32 + ty * 4;
    const int fc   = wx * 64 + tx * 4;

    const int brow = by * 128;
    const int bcol = bx * 128;
    const int lr   = tid >> 2;
    const int lc   = (tid & 3) << 2;

    const float* Ap0 = A + (size_t)(brow + lr)      * K + lc;
    const float* Ap1 = A + (size_t)(brow + lr + 64) * K + lc;
    const float* Bp0 = B + (size_t)(bcol + lr)      * K + lc;
    const float* Bp1 = B + (size_t)(bcol + lr + 64) * K + lc;

    float acc[8][8] = {};

    {
        float4 va0 = *reinterpret_cast<const float4*>(Ap0);
        float4 va1 = *reinterpret_cast<const float4*>(Ap1);
        float4 vb0 = *reinterpret_cast<const float4*>(Bp0);
        float4 vb1 = *reinterpret_cast<const float4*>(Bp1);
        As[0][lc+0][lr]    = va0.x; As[0][lc+1][lr]    = va0.y; As[0][lc+2][lr]    = va0.z; As[0][lc+3][lr]    = va0.w;
        As[0][lc+0][lr+64] = va1.x; As[0][lc+1][lr+64] = va1.y; As[0][lc+2][lr+64] = va1.z; As[0][lc+3][lr+64] = va1.w;
        Bs[0][lc+0][lr]    = vb0.x; Bs[0][lc+1][lr]    = vb0.y; Bs[0][lc+2][lr]    = vb0.z; Bs[0][lc+3][lr]    = vb0.w;
        Bs[0][lc+0][lr+64] = vb1.x; Bs[0][lc+1][lr+64] = vb1.y; Bs[0][lc+2][lr+64] = vb1.z; Bs[0][lc+3][lr+64] = vb1.w;
    }
    __syncthreads();

    int buf = 0;
#pragma unroll 1
    for (int p = 0; p < NP; p++) {
        float4 va0, va1, vb0, vb1;
        const bool more = (p + 1 < NP);
        if (more) {
            int off = (p + 1) * 16;
            va0 = *reinterpret_cast<const float4*>(Ap0 + off);
            va1 = *reinterpret_cast<const float4*>(Ap1 + off);
            vb0 = *reinterpret_cast<const float4*>(Bp0 + off);
            vb1 = *reinterpret_cast<const float4*>(Bp1 + off);
        }
#pragma unroll
        for (int kk = 0; kk < 16; kk++) {
            float4 a0 = *reinterpret_cast<const float4*>(&As[buf][kk][fr]);
            float4 a1 = *reinterpret_cast<const float4*>(&As[buf][kk][fr + 16]);
            float4 b0 = *reinterpret_cast<const float4*>(&Bs[buf][kk][fc]);
            float4 b1 = *reinterpret_cast<const float4*>(&Bs[buf][kk][fc + 32]);
            float ar[8] = {a0.x, a0.y, a0.z, a0.w, a1.x, a1.y, a1.z, a1.w};
            float br[8] = {b0.x, b0.y, b0.z, b0.w, b1.x, b1.y, b1.z, b1.w};
#pragma unroll
            for (int i = 0; i < 8; i++)
#pragma unroll
                for (int j = 0; j < 8; j++)
                    acc[i][j] = fmaf(ar[i], br[j], acc[i][j]);
        }
        if (more) {
            int nb = buf ^ 1;
            As[nb][lc+0][lr]    = va0.x; As[nb][lc+1][lr]    = va0.y; As[nb][lc+2][lr]    = va0.z; As[nb][lc+3][lr]    = va0.w;
            As[nb][lc+0][lr+64] = va1.x; As[nb][lc+1][lr+64] = va1.y; As[nb][lc+2][lr+64] = va1.z; As[nb][lc+3][lr+64] = va1.w;
            Bs[nb][lc+0][lr]    = vb0.x; Bs[nb][lc+1][lr]    = vb0.y; Bs[nb][lc+2][lr]    = vb0.z; Bs[nb][lc+3][lr]    = vb0.w;
            Bs[nb][lc+0][lr+64] = vb1.x; Bs[nb][lc+1][lr+64] = vb1.y; Bs[nb][lc+2][lr+64] = vb1.z; Bs[nb][lc+3][lr+64] = vb1.w;
            __syncthreads();
            buf = nb;
        }
    }

    int gr[2] = {brow + fr, brow + fr + 16};
    int gc[2] = {bcol + fc, bcol + fc + 32};
    float4 bv[2];
#pragma unroll
    for (int qj = 0; qj < 2; qj++)
        bv[qj] = *reinterpret_cast<const float4*>(&bias[gc[qj]]);
#pragma unroll
    for (int qi = 0; qi < 2; qi++)
#pragma unroll
    for (int u = 0; u < 4; u++) {
        size_t rowoff = (size_t)(gr[qi] + u) * N;
#pragma unroll
        for (int qj = 0; qj < 2; qj++) {
            float4 w;
            w.x = tanhf(acc[qi*4+u][qj*4+0] + bv[qj].x);
            w.y = tanhf(acc[qi*4+u][qj*4+1] + bv[qj].y);
            w.z = tanhf(acc[qi*4+u][qj*4+2] + bv[qj].z);
            w.w = tanhf(acc[qi*4+u][qj*4+3] + bv[qj].w);
            *reinterpret_cast<float4*>(&C[rowoff + gc[qj]]) = w;
        }
    }
}

// ================= mma.sync 3xTF32 distance GEMM (base-target ISA) =======================
__device__ __forceinline__ float totf32(float x) {
    uint32_t u;
    asm("cvt.rna.tf32.f32 %0, %1;" : "=r"(u) : "f"(x));
    return __uint_as_float(u);
}

__device__ __forceinline__ void mma8(float* c, const uint32_t* a, const uint32_t* b) {
    asm volatile("mma.sync.aligned.m16n8k8.row.col.f32.tf32.tf32.f32 "
        "{%0,%1,%2,%3}, {%4,%5,%6,%7}, {%8,%9}, {%0,%1,%2,%3};"
        : "+f"(c[0]), "+f"(c[1]), "+f"(c[2]), "+f"(c[3])
        : "r"(a[0]), "r"(a[1]), "r"(a[2]), "r"(a[3]), "r"(b[0]), "r"(b[1]));
}

constexpr int LDT     = 36;                       // smem tile stride (floats): conflict-free
constexpr int TILE_F  = 128 * LDT;                // floats per operand tile
constexpr int SMEM_TC = 4 * TILE_F * 4;           // A_hi A_lo B_hi B_lo -> 73728 bytes

// split-convert a 128x32 fp32 panel into tf32 hi/lo smem tiles (stride LDT)
__device__ __forceinline__ void conv_tile(const float* __restrict__ src, int rowbase, int ld,
                                          int k0, float* __restrict__ hi,
                                          float* __restrict__ lo, int tid) {
#pragma unroll
    for (int j = 0; j < 4; ++j) {
        int slot = tid + 256 * j;            // 0..1023
        int r    = slot >> 3;
        int c4   = (slot & 7) << 2;
        float4 v = *reinterpret_cast<const float4*>(src + (size_t)(rowbase + r) * ld + k0 + c4);
        float4 h, l;
        h.x = totf32(v.x); l.x = totf32(v.x - h.x);
        h.y = totf32(v.y); l.y = totf32(v.y - h.y);
        h.z = totf32(v.z); l.z = totf32(v.z - h.z);
        h.w = totf32(v.w); l.w = totf32(v.w - h.w);
        *reinterpret_cast<float4*>(hi + r * LDT + c4) = h;
        *reinterpret_cast<float4*>(lo + r * LDT + c4) = l;
    }
}

// A=B=g_f [8192,512] -> g_S = -dist (diag -inf), upper-triangle blocks + mirror
__global__ __launch_bounds__(256, 2) void tc_dist_k() {
    constexpr int K   = D_;
    constexpr int NCH = K / 32;
    const float* __restrict__ A = g_f;
    float* __restrict__ C       = g_S;

    int t = blockIdx.x;
    int a = (int)((sqrtf(8.f * (float)t + 1.f) - 1.f) * 0.5f);
    while ((a + 1) * (a + 2) / 2 <= t) ++a;
    while (a * (a + 1) / 2 > t) --a;
    const int bx = a;
    const int by = t - a * (a + 1) / 2;
    const int brow = by * 128;
    const int bcol = bx * 128;

    extern __shared__ float smf[];
    float* Ah = smf;
    float* Al = smf + TILE_F;
    float* Bh = smf + 2 * TILE_F;
    float* Bl = smf + 3 * TILE_F;

    const int tid  = threadIdx.x;
    const int lane = tid & 31;
    const int wid  = tid >> 5;
    const int wm   = wid & 1;              // 0..1 -> 64-row strip
    const int wn   = wid >> 1;             // 0..3 -> 32-col strip
    const int m0w  = wm * 64;
    const int n0w  = wn * 32;
    const int g    = lane >> 2;            // 0..7
    const int t4   = lane & 3;             // 0..3

    float acc[4][4][4];
#pragma unroll
    for (int mt = 0; mt < 4; mt++)
#pragma unroll
        for (int nt = 0; nt < 4; nt++)
#pragma unroll
            for (int e = 0; e < 4; e++) acc[mt][nt][e] = 0.f;

#pragma unroll 1
    for (int c = 0; c < NCH; ++c) {
        conv_tile(A, brow, K, c * 32, Ah, Al, tid);
        conv_tile(A, bcol, K, c * 32, Bh, Bl, tid);
        __syncthreads();

#pragma unroll
        for (int kk = 0; kk < 4; ++kk) {
            const int ko = kk * 8;
            uint32_t bh[4][2], bl[4][2];
#pragma unroll
            for (int nt = 0; nt < 4; nt++) {
                int roff = (n0w + nt * 8 + g) * LDT + ko + t4;
                bh[nt][0] = __float_as_uint(Bh[roff]);
                bh[nt][1] = __float_as_uint(Bh[roff + 4]);
                bl[nt][0] = __float_as_uint(Bl[roff]);
                bl[nt][1] = __float_as_uint(Bl[roff + 4]);
            }
#pragma unroll
            for (int mt = 0; mt < 4; mt++) {
                int r0 = (m0w + mt * 16 + g) * LDT + ko + t4;
                int r8 = r0 + 8 * LDT;
                uint32_t ah[4], al[4];
                ah[0] = __float_as_uint(Ah[r0]);
                ah[1] = __float_as_uint(Ah[r8]);
                ah[2] = __float_as_uint(Ah[r0 + 4]);
                ah[3] = __float_as_uint(Ah[r8 + 4]);
                al[0] = __float_as_uint(Al[r0]);
                al[1] = __float_as_uint(Al[r8]);
                al[2] = __float_as_uint(Al[r0 + 4]);
                al[3] = __float_as_uint(Al[r8 + 4]);
#pragma unroll
                for (int nt = 0; nt < 4; nt++) {
                    mma8(acc[mt][nt], ah, bh[nt]);
                    mma8(acc[mt][nt], ah, bl[nt]);
                    mma8(acc[mt][nt], al, bh[nt]);
                }
            }
        }
        __syncthreads();
    }

    const bool mirror = (bx != by);
#pragma unroll
    for (int mt = 0; mt < 4; mt++) {
        int gi0 = brow + m0w + mt * 16 + g;
        int gi8 = gi0 + 8;
        float sqi0 = g_sqn[gi0], sqi8 = g_sqn[gi8];
#pragma unroll
        for (int nt = 0; nt < 4; nt++) {
            int gj0 = bcol + n0w + nt * 8 + 2 * t4;
            int gj1 = gj0 + 1;
            float sqj0 = g_sqn[gj0], sqj1 = g_sqn[gj1];
            float s0, s1, s2, s3;
            {
                float d2 = fmaxf(sqi0 + sqj0 - 2.f * acc[mt][nt][0], 0.f);
                s0 = (d2 > 1e-9f) ? -sqrtf(d2) : 0.f;
                if (gi0 == gj0) s0 = -INFINITY;
            }
            {
                float d2 = fmaxf(sqi0 + sqj1 - 2.f * acc[mt][nt][1], 0.f);
                s1 = (d2 > 1e-9f) ? -sqrtf(d2) : 0.f;
                if (gi0 == gj1) s1 = -INFINITY;
            }
            {
                float d2 = fmaxf(sqi8 + sqj0 - 2.f * acc[mt][nt][2], 0.f);
                s2 = (d2 > 1e-9f) ? -sqrtf(d2) : 0.f;
                if (gi8 == gj0) s2 = -INFINITY;
            }
            {
                float d2 = fmaxf(sqi8 + sqj1 - 2.f * acc[mt][nt][3], 0.f);
                s3 = (d2 > 1e-9f) ? -sqrtf(d2) : 0.f;
                if (gi8 == gj1) s3 = -INFINITY;
            }
            *reinterpret_cast<float2*>(&C[(size_t)gi0 * NTOK + gj0]) = make_float2(s0, s1);
            *reinterpret_cast<float2*>(&C[(size_t)gi8 * NTOK + gj0]) = make_float2(s2, s3);
            if (mirror) {
                C[(size_t)gj0 * NTOK + gi0] = s0;
                C[(size_t)gj1 * NTOK + gi0] = s1;
                C[(size_t)gj0 * NTOK + gi8] = s2;
                C[(size_t)gj1 * NTOK + gi8] = s3;
            }
        }
    }
}

// ---------------- per-row top-64 + softmax + one-hot scatter ----------------------------
__global__ __launch_bounds__(256) void topk_k(const int* __restrict__ yn, float* __restrict__ out) {
    const int row  = blockIdx.x;
    const float* __restrict__ srow = g_S + (size_t)row * NTOK;
    const int tid  = threadIdx.x;
    const int lane = tid & 31;
    const int warp = tid >> 5;

    float v[32];
#pragma unroll
    for (int k = 0; k < 32; k++) v[k] = srow[tid + (k << 8)];

    float lm = -INFINITY; int li = 0;
#pragma unroll
    for (int k = 0; k < 32; k++) if (v[k] > lm) { lm = v[k]; li = k; }

    __shared__ float swv[8];
    __shared__ int   swi[8];
    __shared__ int   sbroad;
    __shared__ float wval[64];
    __shared__ int   widx[64];

    for (int it = 0; it < 64; it++) {
        float bv = lm;
        int   bi = tid + (li << 8);
#pragma unroll
        for (int o = 16; o; o >>= 1) {
            float ov = __shfl_down_sync(0xffffffffu, bv, o);
            int   oi = __shfl_down_sync(0xffffffffu, bi, o);
            if (ov > bv || (ov == bv && oi < bi)) { bv = ov; bi = oi; }
        }
        if (!lane) { swv[warp] = bv; swi[warp] = bi; }
        __syncthreads();
        if (!tid) {
            float wv = swv[0]; int wi = swi[0];
#pragma unroll
            for (int w = 1; w < 8; w++)
                if (swv[w] > wv || (swv[w] == wv && swi[w] < wi)) { wv = swv[w]; wi = swi[w]; }
            wval[it] = wv; widx[it] = wi; sbroad = wi;
        }
        __syncthreads();
        int wi = sbroad;
        if ((wi & 255) == tid) {
            v[wi >> 8] = -INFINITY;
            lm = -INFINITY; li = 0;
#pragma unroll
            for (int k = 0; k < 32; k++) if (v[k] > lm) { lm = v[k]; li = k; }
        }
    }
    __syncthreads();

    __shared__ float earr[64];
    __shared__ int   larr[64];
    if (tid < 64) {
        earr[tid] = expf(wval[tid] - wval[0]);
        larr[tid] = yn[widx[tid]];
    }
    __syncthreads();

    __shared__ float bins[NC_];
    __shared__ float tot;
    if (!tid) {
        float bb[NC_];
#pragma unroll
        for (int c = 0; c < NC_; c++) bb[c] = 0.f;
        float t = 0.f;
        for (int k = 0; k < 64; k++) { t += earr[k]; bb[larr[k]] += earr[k]; }
        tot = t;
#pragma unroll
        for (int c = 0; c < NC_; c++) bins[c] = bb[c];
    }
    __syncthreads();
    if (tid < NC_) {
        float p = bins[tid] / tot;
        out[(size_t)row * NC_ + tid] = fminf(fmaxf(p, 0.f), 1.f);
    }
}

// ---------------- launcher --------------------------------------------------------------
extern "C" void kernel_launch(void* const* d_in, const int* in_sizes, int n_in,
                              void* d_out, int out_size) {
    (void)in_sizes; (void)n_in; (void)out_size;
    const float* x     = (const float*)d_in[0];
    // d_in[1] is x_n == x elementwise (reference guarantees it) -> features computed once
    const int*   y_n   = (const int*)  d_in[2];
    const float* ibn_g = (const float*)d_in[3];
    const float* ibn_b = (const float*)d_in[4];
    const float* W1    = (const float*)d_in[5];
    const float* b1    = (const float*)d_in[6];
    const float* g1    = (const float*)d_in[7];
    const float* bb1   = (const float*)d_in[8];
    const float* W2    = (const float*)d_in[9];
    const float* b2    = (const float*)d_in[10];
    const float* g2    = (const float*)d_in[11];
    const float* bb2   = (const float*)d_in[12];
    float* out = (float*)d_out;

    // opt into >48KB dynamic smem (host-side attribute; not a stream op)
    cudaFuncSetAttribute(tc_dist_k, cudaFuncAttributeMaxDynamicSharedMemorySize, SMEM_TC);

    // input BN
    colstats_k<0><<<dim3(D_ / 32, NSPLIT), 256>>>(x);
    colfinish_k<<<(D_ + 255) / 256, 256>>>(D_, ibn_g, ibn_b);
    bn_apply_k<0><<<2048, 256>>>(x);

    // layer 1: Linear -> tanh -> BN   (fp32 SIMT: feature numerics match baseline)
    gemm_k<0><<<dim3(H1_ / 128, NTOK / 128), 256>>>(W1, b1);
    colstats_k<1><<<dim3(H1_ / 32, NSPLIT), 256>>>(nullptr);
    colfinish_k<<<(H1_ + 255) / 256, 256>>>(H1_, g1, bb1);
    bn_apply_k<1><<<2048, 256>>>(nullptr);

    // layer 2: Linear -> tanh -> BN
    gemm_k<1><<<dim3(H2_ / 128, NTOK / 128), 256>>>(W2, b2);
    colstats_k<2><<<dim3(H2_ / 32, NSPLIT), 256>>>(nullptr);
    colfinish_k<<<(H2_ + 255) / 256, 256>>>(H2_, g2, bb2);
    bn_apply_k<2><<<2048, 256>>>(nullptr);

    // NONA: sim matrix (tensor-core 3xTF32, upper-tri + mirror) + top-64 softmax
    rowsq_k<<<NTOK / 8, 256>>>();
    constexpr int NBLK = NTOK / 128;                        // 64
    tc_dist_k<<<NBLK * (NBLK + 1) / 2, 256, SMEM_TC>>>();
    topk_k<<<NTOK, 256>>>(y_n, out);
}